// round 10
// baseline (speedup 1.0000x reference)
#include <cuda_runtime.h>
#include <cstdint>

// Flag: 1 if idx buffer is int64, 0 if int32.
__device__ int g_idx_is64;

// Detect idx dtype: for int64 indices in [0, 1e6) the high words are all 0;
// for random int32 indices the odd words are ~never all zero across 64 entries.
__global__ void detect_idx_kernel(const unsigned int* __restrict__ idx_words) {
    int is64 = 1;
    #pragma unroll 1
    for (int k = 0; k < 64; ++k) {
        if (idx_words[2 * k + 1] != 0u) { is64 = 0; break; }
    }
    g_idx_is64 = is64;
}

// L2 access policy: evict_last (keep the 64MB values table resident in L2).
__device__ __forceinline__ unsigned long long make_evict_last_policy() {
    unsigned long long pol;
    asm volatile("createpolicy.fractional.L2::evict_last.b64 %0, 1.0;" : "=l"(pol));
    return pol;
}

// 16B gather load, L2-resident via cache-hint policy.
__device__ __forceinline__ float4 ldg4_L2_resident(const float* p, unsigned long long pol) {
    float4 v;
    asm volatile("ld.global.nc.L2::cache_hint.v4.f32 {%0,%1,%2,%3}, [%4], %5;"
                 : "=f"(v.x), "=f"(v.y), "=f"(v.z), "=f"(v.w)
                 : "l"(p), "l"(pol));
    return v;
}

// One neuron per 16 threads, float4-cooperative gather:
//   lane l: j = l&3 (element chunk), k = l>>2 (row)
//   2 x LDG.128 cover all 8 fan-in rows for the group (vs 8 scalar loads)
//   2 x shfl_xor (4, 8) reduce over rows -> lane l holds s[4j..4j+3]
//   GEMV: lane d owns W row d; s chunks broadcast via 16 shfls; y = tanh(Ws+b)
__global__ __launch_bounds__(256)
void weighted_atom_kernel(const float* __restrict__ values,
                          const void*  __restrict__ idx_raw,
                          const float* __restrict__ W,
                          const float* __restrict__ bvec,
                          float* __restrict__ out,
                          int N)
{
    const int gid  = blockIdx.x * blockDim.x + threadIdx.x;
    const int n    = gid >> 4;
    const int lane = gid & 15;
    if (n >= N) return;   // grid sized exactly; never taken (keeps shfl safe)

    const unsigned long long pol = make_evict_last_policy();

    // ---- fetch the 8 fan-in row indices (values < 2^20 -> int is safe) ----
    int rows[8];
    if (g_idx_is64) {
        const int4* p = (const int4*)((const long long*)idx_raw + (long long)n * 8);
        int4 q0 = p[0], q1 = p[1], q2 = p[2], q3 = p[3];
        rows[0] = q0.x; rows[1] = q0.z;   // low words of each int64
        rows[2] = q1.x; rows[3] = q1.z;
        rows[4] = q2.x; rows[5] = q2.z;
        rows[6] = q3.x; rows[7] = q3.z;
    } else {
        const int4* p = (const int4*)((const int*)idx_raw + n * 8);
        int4 q0 = p[0], q1 = p[1];
        rows[0] = q0.x; rows[1] = q0.y; rows[2] = q0.z; rows[3] = q0.w;
        rows[4] = q1.x; rows[5] = q1.y; rows[6] = q1.z; rows[7] = q1.w;
    }

    const int j = lane & 3;     // element chunk [4j, 4j+3]
    const int k = lane >> 2;    // row within first half

    // ---- cooperative gather: 2 x LDG.128 cover rows 0..7 ----
    float4 ga = ldg4_L2_resident(values + (size_t)rows[k]     * 16 + j * 4, pol);
    float4 gb = ldg4_L2_resident(values + (size_t)rows[4 + k] * 16 + j * 4, pol);

    // ---- streaming loads of W (4 x LDG.128, evict-first) + b ----
    const float4* Wrow4 = (const float4*)(W + (size_t)n * 256 + (size_t)lane * 16);
    float4 w0 = __ldcs(Wrow4 + 0);
    float4 w1 = __ldcs(Wrow4 + 1);
    float4 w2 = __ldcs(Wrow4 + 2);
    float4 w3 = __ldcs(Wrow4 + 3);
    float  y  = __ldcs(bvec + gid);   // b[n*16 + lane]

    // ---- reduce over rows: lanes {j, j+4, j+8, j+12} hold rows {k, k+4} ----
    float4 s4;
    s4.x = ga.x + gb.x; s4.y = ga.y + gb.y; s4.z = ga.z + gb.z; s4.w = ga.w + gb.w;
    const unsigned mask = 0xFFFFFFFFu;
    s4.x += __shfl_xor_sync(mask, s4.x, 4, 16);
    s4.y += __shfl_xor_sync(mask, s4.y, 4, 16);
    s4.z += __shfl_xor_sync(mask, s4.z, 4, 16);
    s4.w += __shfl_xor_sync(mask, s4.w, 4, 16);
    s4.x += __shfl_xor_sync(mask, s4.x, 8, 16);
    s4.y += __shfl_xor_sync(mask, s4.y, 8, 16);
    s4.z += __shfl_xor_sync(mask, s4.z, 8, 16);
    s4.w += __shfl_xor_sync(mask, s4.w, 8, 16);
    // lane l now holds s[4j .. 4j+3]; chunk c lives in lanes c, c+4, c+8, c+12

    // ---- GEMV: broadcast chunk c from lane c of the group ----
    y += w0.x * __shfl_sync(mask, s4.x, 0, 16);
    y += w0.y * __shfl_sync(mask, s4.y, 0, 16);
    y += w0.z * __shfl_sync(mask, s4.z, 0, 16);
    y += w0.w * __shfl_sync(mask, s4.w, 0, 16);
    y += w1.x * __shfl_sync(mask, s4.x, 1, 16);
    y += w1.y * __shfl_sync(mask, s4.y, 1, 16);
    y += w1.z * __shfl_sync(mask, s4.z, 1, 16);
    y += w1.w * __shfl_sync(mask, s4.w, 1, 16);
    y += w2.x * __shfl_sync(mask, s4.x, 2, 16);
    y += w2.y * __shfl_sync(mask, s4.y, 2, 16);
    y += w2.z * __shfl_sync(mask, s4.z, 2, 16);
    y += w2.w * __shfl_sync(mask, s4.w, 2, 16);
    y += w3.x * __shfl_sync(mask, s4.x, 3, 16);
    y += w3.y * __shfl_sync(mask, s4.y, 3, 16);
    y += w3.z * __shfl_sync(mask, s4.z, 3, 16);
    y += w3.w * __shfl_sync(mask, s4.w, 3, 16);

    __stcs(out + gid, tanhf(y));
}

extern "C" void kernel_launch(void* const* d_in, const int* in_sizes, int n_in,
                              void* d_out, int out_size)
{
    // metadata order == setup_inputs order: values, idx, W, b
    const float* values = (const float*)d_in[0];
    const void*  idx    = d_in[1];
    const float* W      = (const float*)d_in[2];
    const float* bvec   = (const float*)d_in[3];
    float* out          = (float*)d_out;

    const int N = in_sizes[3] / 16;   // b has N*16 elements

    detect_idx_kernel<<<1, 1>>>((const unsigned int*)idx);

    const int threads = 256;
    const int total   = N * 16;
    const int blocks  = (total + threads - 1) / threads;
    weighted_atom_kernel<<<blocks, threads>>>(values, idx, W, bvec, out, N);
}